// round 1
// baseline (speedup 1.0000x reference)
#include <cuda_runtime.h>

#define NN 128
#define TRI (NN * (NN + 1) / 2)   // 8256 cells per triangular table

__device__ __forceinline__ int triRow(int a) {
    // index of cell (a, a) in triangular packing: sum_{r<a} (NN - r)
    return a * (2 * NN - a + 1) / 2;
}

__global__ void __launch_bounds__(1024, 1)
eisner_kernel(const float* __restrict__ vin_all,
              float* __restrict__ out,
              int has_bt, int bt_off)
{
    extern __shared__ float sm[];
    float* T00 = sm;               // S[:,:,0,0]
    float* T01 = sm + TRI;         // S[:,:,0,1]
    float* T10 = sm + 2 * TRI;     // S[:,:,1,0]
    float* T11 = sm + 3 * TRI;     // S[:,:,1,1]

    const float NEG = -9999.0f;
    const float THRESH = -9000.0f;

    const int b = blockIdx.x;
    const float* __restrict__ vin = vin_all + (size_t)b * NN * NN;
    float* __restrict__ outS = out + (size_t)b * NN * NN * 4;
    float* __restrict__ outB = out + (size_t)bt_off + (size_t)b * NN * NN * 4;

    const int tid = threadIdx.x;

    // ---- init: triangular tables = NEG, diagonal = 0 ----
    for (int t = tid; t < 4 * TRI; t += blockDim.x) sm[t] = NEG;
    __syncthreads();
    for (int i = tid; i < NN; i += blockDim.x) {
        int d = triRow(i);
        T00[d] = 0.0f; T01[d] = 0.0f; T10[d] = 0.0f; T11[d] = 0.0f;
    }
    // ---- init output: scores = NEG (diag 0), backtrace = 0 ----
    for (int t = tid; t < NN * NN * 4; t += blockDim.x) {
        int i = t >> 9;               // t / (NN*4)
        int j = (t >> 2) & (NN - 1);  // (t/4) % NN
        outS[t] = (i == j) ? 0.0f : NEG;
    }
    if (has_bt) {
        for (int t = tid; t < NN * NN * 4; t += blockDim.x) outB[t] = 0.0f;
    }
    __syncthreads();

    const int warp = tid >> 5;
    const int lane = tid & 31;
    const int nw   = blockDim.x >> 5;

    for (int k = 1; k < NN; ++k) {
        const int nspans = NN - k;
        for (int s = warp; s < nspans; s += nw) {
            const int i = s;
            const int j = s + k;
            const float vL = vin[j * NN + i];   // left arc  (head j)
            const float vR = vin[i * NN + j];   // right arc (head i)
            const int rpi = triRow(i);          // index of (i,i)

            float v00 = NEG, v10 = NEG, v01 = NEG, v11 = NEG;
            int   m00 = NN,  m10 = NN,  m01 = NN,  m11 = NN;

            // fused pass over split index m (q = i+m)
            for (int m = lane; m < k; m += 32) {
                const int q = i + m;
                const int triq  = triRow(q) + (j - q);       // tri(q, j)
                const int triq1 = triq + (NN - 1 - q);       // tri(q+1, j)
                // incomplete spans: base = S[i,q,1,1] + S[q+1,j,0,1]
                const float base = T11[rpi + m] + T01[triq1];
                float a0 = (base + vL) + 5.0f; a0 = fmaxf(a0, NEG);
                float a1 = (base + vR) + 5.0f; a1 = fmaxf(a1, NEG);
                if (a0 > v00) { v00 = a0; m00 = m; }
                if (a1 > v10) { v10 = a1; m10 = m; }
                if (m >= 1) {
                    // complete spans (mid splits only)
                    float c01 = T01[rpi + m] + T00[triq];
                    c01 = fmaxf(c01, NEG);
                    if (c01 > v01) { v01 = c01; m01 = m; }
                    float c11 = T10[rpi + m] + T11[triq];
                    c11 = fmaxf(c11, NEG);
                    if (c11 > v11) { v11 = c11; m11 = m; }
                }
            }

            // 4-way butterfly argmax reduce, first-occurrence tie-break
            #pragma unroll
            for (int off = 16; off; off >>= 1) {
                float ov; int om;
                ov = __shfl_xor_sync(0xffffffffu, v00, off);
                om = __shfl_xor_sync(0xffffffffu, m00, off);
                if (ov > v00 || (ov == v00 && om < m00)) { v00 = ov; m00 = om; }
                ov = __shfl_xor_sync(0xffffffffu, v10, off);
                om = __shfl_xor_sync(0xffffffffu, m10, off);
                if (ov > v10 || (ov == v10 && om < m10)) { v10 = ov; m10 = om; }
                ov = __shfl_xor_sync(0xffffffffu, v01, off);
                om = __shfl_xor_sync(0xffffffffu, m01, off);
                if (ov > v01 || (ov == v01 && om < m01)) { v01 = ov; m01 = om; }
                ov = __shfl_xor_sync(0xffffffffu, v11, off);
                om = __shfl_xor_sync(0xffffffffu, m11, off);
                if (ov > v11 || (ov == v11 && om < m11)) { v11 = ov; m11 = om; }
            }

            // sequential-update quirks of the reference:
            // (0,1) at q=i sees the (0,0) cell after ONLY the q=i update
            float base0 = T11[rpi] + T01[triRow(i + 1) + (j - i - 1)];
            float p000 = (base0 + vL) + 5.0f;
            p000 = fmaxf(p000, NEG);
            const float part00 = (p000 > THRESH) ? p000 : NEG;
            if (part00 > v01 || (part00 == v01 && 0 < m01)) { v01 = part00; m01 = 0; }
            // (1,1) at q=j sees the fully updated (1,0) cell
            const float new10 = (v10 > THRESH) ? v10 : NEG;
            if (new10 > v11) { v11 = new10; m11 = k; }   // strict > keeps earlier q on tie

            if (lane == 0) {
                const float s00 = (v00 > THRESH) ? v00 : NEG;
                const float s10 = (v10 > THRESH) ? v10 : NEG;
                const float s01 = (v01 > THRESH) ? v01 : NEG;
                const float s11 = (v11 > THRESH) ? v11 : NEG;
                const int t00 = (v00 > THRESH) ? (i + m00) : 0;
                const int t10 = (v10 > THRESH) ? (i + m10) : 0;
                const int t01 = (v01 > THRESH) ? (i + m01) : 0;
                const int t11 = (v11 > THRESH) ? (i + m11) : 0;

                const int tij = rpi + k;   // tri(i, j)
                T00[tij] = s00; T01[tij] = s01; T10[tij] = s10; T11[tij] = s11;

                const size_t o = ((size_t)(i * NN + j)) * 4;
                outS[o + 0] = s00; outS[o + 1] = s01;
                outS[o + 2] = s10; outS[o + 3] = s11;
                if (has_bt) {
                    outB[o + 0] = (float)t00; outB[o + 1] = (float)t01;
                    outB[o + 2] = (float)t10; outB[o + 3] = (float)t11;
                }
            }
        }
        __syncthreads();
    }
}

extern "C" void kernel_launch(void* const* d_in, const int* in_sizes, int n_in,
                              void* d_out, int out_size)
{
    const float* vin = (const float*)d_in[0];
    float* out = (float*)d_out;
    const int B = in_sizes[0] / (NN * NN);          // 64
    const int score_elems = B * NN * NN * 4;        // scores region size
    const int has_bt = (out_size >= 2 * score_elems) ? 1 : 0;

    const int smem_bytes = 4 * TRI * sizeof(float); // 132096 B
    cudaFuncSetAttribute(eisner_kernel,
                         cudaFuncAttributeMaxDynamicSharedMemorySize, smem_bytes);
    eisner_kernel<<<B, 1024, smem_bytes>>>(vin, out, has_bt, score_elems);
}

// round 2
// speedup vs baseline: 2.9938x; 2.9938x over previous
#include <cuda_runtime.h>

#define NN 128
#define TRI (NN * (NN + 1) / 2)   // 8256 cells per triangular table

__device__ __forceinline__ int triRow(int a) {
    // index of cell (a, a) in triangular packing
    return a * (2 * NN - a + 1) / 2;
}

#define NEGC    (-9999.0f)
#define THRESHC (-9000.0f)

// One DP step for span width k, with G lanes cooperating per span.
// A warp covers 32/G spans; reductions are log2(G) butterfly steps.
template<int G>
__device__ __forceinline__ void step_body(
    const float* __restrict__ T00, const float* __restrict__ T01,
    const float* __restrict__ T10, const float* __restrict__ T11,
    float* __restrict__ W00, float* __restrict__ W01,
    float* __restrict__ W10, float* __restrict__ W11,
    const float* __restrict__ vin,
    float* __restrict__ outS, float* __restrict__ outB,
    int has_bt, int k, int tid)
{
    const int nspans = NN - k;
    // whole-warp early out (converged: all lanes of the warp share this test)
    if (((tid & ~31) / G) >= nspans) return;

    const int gid_raw = tid / G;
    const int lig = tid % G;
    const bool lead = (lig == 0) && (gid_raw < nspans);
    const int i = min(gid_raw, nspans - 1);   // clamp dup groups (writes gated by lead)
    const int j = i + k;

    const float vL = vin[j * NN + i];   // left arc  (head j)
    const float vR = vin[i * NN + j];   // right arc (head i)
    const int rpi = triRow(i);

    const float NINF = __int_as_float(0xff800000);
    float v00 = NINF, v10 = NINF, v01 = NINF, v11 = NINF;
    int   m00 = NN,   m10 = NN,   m01 = NN,   m11 = NN;

    // incremental triangular indices: q = i + m, m = lig, lig+G, ...
    int m   = lig;
    int q0  = i + lig;
    int A   = triRow(q0) + (j - q0);        // tri(q, j)
    int B   = A + (NN - 1 - q0);            // tri(q+1, j)
    int dA  = (G * (257 - 2 * q0 - G)) / 2 - G;   // A(next) - A(cur)
    int idx = rpi + lig;                    // rpi + m

    for (; m < k; m += G) {
        const float s11 = T11[idx];
        const float s01 = T01[B];
        const float base = s11 + s01;
        // preserve reference rounding order: ((s11+s01)+v)+5.0
        float a0 = (base + vL) + 5.0f;
        float a1 = (base + vR) + 5.0f;
        if (a0 > v00) { v00 = a0; m00 = m; }
        if (a1 > v10) { v10 = a1; m10 = m; }
        if (m >= 1) {
            float c01 = T01[idx] + T00[A];
            float c11 = T10[idx] + T11[A];
            if (c01 > v01) { v01 = c01; m01 = m; }
            if (c11 > v11) { v11 = c11; m11 = m; }
        }
        A += dA; B += dA - G; dA -= G * G; idx += G;
    }

    if (G > 1) {
        #pragma unroll
        for (int off = G / 2; off; off >>= 1) {
            float ov; int om;
            ov = __shfl_xor_sync(0xffffffffu, v00, off);
            om = __shfl_xor_sync(0xffffffffu, m00, off);
            if (ov > v00 || (ov == v00 && om < m00)) { v00 = ov; m00 = om; }
            ov = __shfl_xor_sync(0xffffffffu, v10, off);
            om = __shfl_xor_sync(0xffffffffu, m10, off);
            if (ov > v10 || (ov == v10 && om < m10)) { v10 = ov; m10 = om; }
            ov = __shfl_xor_sync(0xffffffffu, v01, off);
            om = __shfl_xor_sync(0xffffffffu, m01, off);
            if (ov > v01 || (ov == v01 && om < m01)) { v01 = ov; m01 = om; }
            ov = __shfl_xor_sync(0xffffffffu, v11, off);
            om = __shfl_xor_sync(0xffffffffu, m11, off);
            if (ov > v11 || (ov == v11 && om < m11)) { v11 = ov; m11 = om; }
        }
    }

    if (lead) {
        // sequential-update quirks of the reference:
        // (0,1) at q=i sees the (0,0) cell after ONLY the q=i update
        float base0 = T11[rpi] + T01[rpi + (NN - i) + (k - 1)];
        float p000 = (base0 + vL) + 5.0f;
        p000 = fmaxf(p000, NEGC);
        const float part00 = (p000 > THRESHC) ? p000 : NEGC;
        if (part00 > v01 || (part00 == v01 && 0 < m01)) { v01 = part00; m01 = 0; }
        // (1,1) at q=j sees the fully updated (1,0) cell
        const float new10 = (v10 > THRESHC) ? v10 : NEGC;
        if (new10 > v11) { v11 = new10; m11 = k; }

        const float s00 = (v00 > THRESHC) ? v00 : NEGC;
        const float s10 = (v10 > THRESHC) ? v10 : NEGC;
        const float s01 = (v01 > THRESHC) ? v01 : NEGC;
        const float s11 = (v11 > THRESHC) ? v11 : NEGC;
        const int t00 = (v00 > THRESHC) ? (i + m00) : 0;
        const int t10 = (v10 > THRESHC) ? (i + m10) : 0;
        const int t01 = (v01 > THRESHC) ? (i + m01) : 0;
        const int t11 = (v11 > THRESHC) ? (i + m11) : 0;

        const int tij = rpi + k;   // tri(i, j)
        W00[tij] = s00; W01[tij] = s01; W10[tij] = s10; W11[tij] = s11;

        const size_t o = ((size_t)(i * NN + j)) * 4;
        outS[o + 0] = s00; outS[o + 1] = s01;
        outS[o + 2] = s10; outS[o + 3] = s11;
        if (has_bt) {
            outB[o + 0] = (float)t00; outB[o + 1] = (float)t01;
            outB[o + 2] = (float)t10; outB[o + 3] = (float)t11;
        }
    }
}

__global__ void __launch_bounds__(512, 1)
eisner_kernel(const float* __restrict__ vin_all,
              float* __restrict__ out,
              int has_bt, int bt_off)
{
    extern __shared__ float sm[];
    float* T00 = sm;               // S[:,:,0,0]
    float* T01 = sm + TRI;         // S[:,:,0,1]
    float* T10 = sm + 2 * TRI;     // S[:,:,1,0]
    float* T11 = sm + 3 * TRI;     // S[:,:,1,1]

    const int b = blockIdx.x;
    const float* __restrict__ vin = vin_all + (size_t)b * NN * NN;
    float* __restrict__ outS = out + (size_t)b * NN * NN * 4;
    float* __restrict__ outB = out + (size_t)bt_off + (size_t)b * NN * NN * 4;

    const int tid = threadIdx.x;

    // ---- init: triangular tables = NEG, diagonal = 0 ----
    for (int t = tid; t < 4 * TRI; t += blockDim.x) sm[t] = NEGC;
    __syncthreads();
    for (int i = tid; i < NN; i += blockDim.x) {
        int d = triRow(i);
        T00[d] = 0.0f; T01[d] = 0.0f; T10[d] = 0.0f; T11[d] = 0.0f;
    }
    // ---- init output: scores = NEG (diag 0), backtrace = 0 ----
    for (int t = tid; t < NN * NN * 4; t += blockDim.x) {
        int i = t >> 9;               // t / (NN*4)
        int j = (t >> 2) & (NN - 1);  // (t/4) % NN
        outS[t] = (i == j) ? 0.0f : NEGC;
    }
    if (has_bt) {
        for (int t = tid; t < NN * NN * 4; t += blockDim.x) outB[t] = 0.0f;
    }
    __syncthreads();

    for (int k = 1; k < NN; ++k) {
        if (k <= 12)
            step_body<1 >(T00, T01, T10, T11, T00, T01, T10, T11, vin, outS, outB, has_bt, k, tid);
        else if (k <= 24)
            step_body<2 >(T00, T01, T10, T11, T00, T01, T10, T11, vin, outS, outB, has_bt, k, tid);
        else if (k <= 64)
            step_body<4 >(T00, T01, T10, T11, T00, T01, T10, T11, vin, outS, outB, has_bt, k, tid);
        else if (k <= 96)
            step_body<8 >(T00, T01, T10, T11, T00, T01, T10, T11, vin, outS, outB, has_bt, k, tid);
        else
            step_body<16>(T00, T01, T10, T11, T00, T01, T10, T11, vin, outS, outB, has_bt, k, tid);
        __syncthreads();
    }
}

extern "C" void kernel_launch(void* const* d_in, const int* in_sizes, int n_in,
                              void* d_out, int out_size)
{
    const float* vin = (const float*)d_in[0];
    float* out = (float*)d_out;
    const int B = in_sizes[0] / (NN * NN);          // 64
    const int score_elems = B * NN * NN * 4;        // scores region size
    const int has_bt = (out_size >= 2 * score_elems) ? 1 : 0;

    const int smem_bytes = 4 * TRI * sizeof(float); // 132096 B
    cudaFuncSetAttribute(eisner_kernel,
                         cudaFuncAttributeMaxDynamicSharedMemorySize, smem_bytes);
    eisner_kernel<<<B, 512, smem_bytes>>>(vin, out, has_bt, score_elems);
}